// round 11
// baseline (speedup 1.0000x reference)
#include <cuda_runtime.h>

#define BATCH 4096
#define T_LEN 256
#define I1 38
#define H1 50
#define H2 15
#define NC 14
#define BB 16         // batch rows per CTA; grid 256
#define CHUNK 8       // bb per register-chunk in gate loops
#define THREADS 288
#define L2_BASE 224   // L2 threads [224,284): warps 7-8, never mixed with L1

// Padded row widths for 16B smem loads (pads zeroed once, never rewritten)
#define XP 40   // I1=38 -> 40
#define HP1 52  // H1=50 -> 52
#define HP2 16  // H2=15 -> 16
#define GP 20   // gate-exchange row pad (20 floats = 80B, conflict-free .128)
#define NXEL (BB * I1)   // 608

typedef unsigned long long ull;

struct __align__(16) Smem {
    float x[2][BB][XP];      // double-buffered input tile
    float h1[2][BB][HP1];    // DOUBLE-buffered layer-1 hidden state
    float h2[2][BB][HP2];    // DOUBLE-buffered layer-2 hidden state
    float g1s[H1][4][GP];    // warp-local gate exchange, layer 1
    float g2s[H2][4][GP];    // warp-local gate exchange, layer 2
};

__device__ __forceinline__ ull pack2(float lo, float hi) {
    ull r;
    asm("mov.b64 %0, {%1, %2};" : "=l"(r) : "f"(lo), "f"(hi));
    return r;
}
__device__ __forceinline__ void unpack2(ull p, float& lo, float& hi) {
    asm("mov.b64 {%0, %1}, %2;" : "=f"(lo), "=f"(hi) : "l"(p));
}
// packed dual FMA on the fp32 pipe (FFMA2)
__device__ __forceinline__ ull ffma2(ull a, ull b, ull c) {
    ull d;
    asm("fma.rn.f32x2 %0, %1, %2, %3;" : "=l"(d) : "l"(a), "l"(b), "l"(c));
    return d;
}

__device__ __forceinline__ float sigm(float v) {
    return __fdividef(1.0f, 1.0f + __expf(-v));
}
__device__ __forceinline__ float tanh_f(float v) {
    float a = fabsf(v);
    float e = __expf(-2.0f * a);
    float t = __fdividef(1.0f - e, 1.0f + e);
    return copysignf(t, v);
}

__global__ void __launch_bounds__(THREADS)
lstm2_kernel(const float* __restrict__ x,
             const float* __restrict__ w_ih1, const float* __restrict__ w_hh1,
             const float* __restrict__ b_ih1, const float* __restrict__ b_hh1,
             const float* __restrict__ w_ih2, const float* __restrict__ w_hh2,
             const float* __restrict__ b_ih2, const float* __restrict__ b_hh2,
             const float* __restrict__ w_fc,  const float* __restrict__ b_fc,
             float* __restrict__ out)
{
    __shared__ Smem sm;
    const int tid   = threadIdx.x;
    const int bbase = blockIdx.x * BB;

    for (int i = tid; i < (int)(sizeof(Smem) / 4); i += THREADS)
        ((float*)&sm)[i] = 0.0f;

    const bool isL1 = (tid < 4 * H1);                       // 200 threads
    const bool isL2 = (tid >= L2_BASE) && (tid < L2_BASE + 4 * H2);

    // gate-major-within-unit mapping: 4 adjacent lanes = 4 gates of one unit
    const int lg  = tid & 3;                                // gate index i,f,g,o
    const int u1v = isL1 ? (tid >> 2) : 0;                  // L1 unit 0..49
    const int u2v = isL2 ? ((tid - L2_BASE) >> 2) : 0;      // L2 unit 0..14
    const int lg2 = isL2 ? ((tid - L2_BASE) & 3) : 0;

    // syncwarp masks (partial warps: warp 6 lanes 0-7 L1; warp 8 lanes 0-27 L2)
    const unsigned m1 = (tid < 192) ? 0xffffffffu : 0x000000ffu;
    const unsigned m2 = (tid < 256) ? 0xffffffffu : 0x0fffffffu;

    // ---- packed weight pairs (roles share) ----
    ull wreg2[46];
    #pragma unroll
    for (int k = 0; k < 46; k++) wreg2[k] = 0ull;

    float bias = 0.0f;
    if (isL1) {
        const int g = lg * H1 + u1v;                        // torch row
        #pragma unroll
        for (int p = 0; p < XP / 2; p++) {
            int e = 2 * p;
            float lo = (e     < I1) ? w_ih1[g * I1 + e]     : 0.0f;
            float hi = (e + 1 < I1) ? w_ih1[g * I1 + e + 1] : 0.0f;
            wreg2[p] = pack2(lo, hi);
        }
        #pragma unroll
        for (int p = 0; p < HP1 / 2; p++) {
            int e = 2 * p;
            float lo = (e     < H1) ? w_hh1[g * H1 + e]     : 0.0f;
            float hi = (e + 1 < H1) ? w_hh1[g * H1 + e + 1] : 0.0f;
            wreg2[XP / 2 + p] = pack2(lo, hi);
        }
        bias = b_ih1[g] + b_hh1[g];
    } else if (isL2) {
        const int g = lg2 * H2 + u2v;
        #pragma unroll
        for (int p = 0; p < HP1 / 2; p++) {
            int e = 2 * p;
            float lo = (e     < H1) ? w_ih2[g * H1 + e]     : 0.0f;
            float hi = (e + 1 < H1) ? w_ih2[g * H1 + e + 1] : 0.0f;
            wreg2[p] = pack2(lo, hi);
        }
        #pragma unroll
        for (int p = 0; p < HP2 / 2; p++) {
            int e = 2 * p;
            float lo = (e     < H2) ? w_hh2[g * H2 + e]     : 0.0f;
            float hi = (e + 1 < H2) ? w_hh2[g * H2 + e + 1] : 0.0f;
            wreg2[HP1 / 2 + p] = pack2(lo, hi);
        }
        bias = b_ih2[g] + b_hh2[g];
    }

    // per-lane cell state: batches 4*lg + j (L1) / 4*lg2 + j (L2)
    float c1[4] = {0.f, 0.f, 0.f, 0.f};
    float c2[4] = {0.f, 0.f, 0.f, 0.f};

    // ---- x register prefetch: 3 slots ----
    int xb[3], xk[3];
    bool xv[3];
    #pragma unroll
    for (int s = 0; s < 3; s++) {
        int idx = tid + THREADS * s;
        xv[s] = idx < NXEL;
        int bb = xv[s] ? (idx / I1) : 0;
        xb[s] = bb; xk[s] = xv[s] ? (idx - bb * I1) : 0;
    }
    float xr[3] = {0.f, 0.f, 0.f};

    __syncthreads();   // smem zero done
    #pragma unroll
    for (int s = 0; s < 3; s++)
        if (xv[s])
            sm.x[0][xb[s]][xk[s]] = x[((long)(bbase + xb[s]) * T_LEN + 0) * I1 + xk[s]];
    #pragma unroll
    for (int s = 0; s < 3; s++)
        if (xv[s])
            xr[s] = x[((long)(bbase + xb[s]) * T_LEN + 1) * I1 + xk[s]];
    __syncthreads();

    // ============ main recurrence: ONE full barrier per step ============
    // At step t: rb=(t+1)&1 holds h1(t-1); L1 writes h1[wb=t&1].
    // L2 (computing its step t-1) reads h1[rb], h2[wb]=h2(t-2), writes h2[rb].
    // Loop runs t=0..T_LEN inclusive; t==T_LEN is the L2 drain iteration.
    for (int t = 0; t <= T_LEN; ++t) {
        const int rb  = (t + 1) & 1;
        const int wb  = t & 1;
        const int buf = t & 1;

        // x: commit x(t+1), prefetch x(t+2)
        if (t + 1 < T_LEN) {
            #pragma unroll
            for (int s = 0; s < 3; s++)
                if (xv[s]) sm.x[buf ^ 1][xb[s]][xk[s]] = xr[s];
        }
        if (t + 2 < T_LEN) {
            #pragma unroll
            for (int s = 0; s < 3; s++)
                if (xv[s])
                    xr[s] = x[((long)(bbase + xb[s]) * T_LEN + (t + 2)) * I1 + xk[s]];
        }

        if (isL1 && t < T_LEN) {
            // ---- gates: row lg*H1+u1v, all 16 batches ----
            float gv[16];
            for (int cb = 0; cb < BB; cb += CHUNK) {
                ull acc[CHUNK];
                #pragma unroll
                for (int j = 0; j < CHUNK; j++) acc[j] = pack2(bias, 0.0f);
                #pragma unroll
                for (int k4 = 0; k4 < XP / 4; k4++) {
                    #pragma unroll
                    for (int j = 0; j < CHUNK; j++) {
                        ulonglong2 v = *((const ulonglong2*)&sm.x[buf][cb + j][4 * k4]);
                        acc[j] = ffma2(v.x, wreg2[2 * k4],     acc[j]);
                        acc[j] = ffma2(v.y, wreg2[2 * k4 + 1], acc[j]);
                    }
                }
                #pragma unroll
                for (int k4 = 0; k4 < HP1 / 4; k4++) {
                    #pragma unroll
                    for (int j = 0; j < CHUNK; j++) {
                        ulonglong2 v = *((const ulonglong2*)&sm.h1[rb][cb + j][4 * k4]);
                        acc[j] = ffma2(v.x, wreg2[XP / 2 + 2 * k4],     acc[j]);
                        acc[j] = ffma2(v.y, wreg2[XP / 2 + 2 * k4 + 1], acc[j]);
                    }
                }
                #pragma unroll
                for (int j = 0; j < CHUNK; j++) {
                    float lo, hi; unpack2(acc[j], lo, hi);
                    gv[cb + j] = lo + hi;
                }
            }
            // ---- warp-local exchange: 4 STS.128 / syncwarp / 4 LDS.128 ----
            *(float4*)&sm.g1s[u1v][lg][0]  = make_float4(gv[0],  gv[1],  gv[2],  gv[3]);
            *(float4*)&sm.g1s[u1v][lg][4]  = make_float4(gv[4],  gv[5],  gv[6],  gv[7]);
            *(float4*)&sm.g1s[u1v][lg][8]  = make_float4(gv[8],  gv[9],  gv[10], gv[11]);
            *(float4*)&sm.g1s[u1v][lg][12] = make_float4(gv[12], gv[13], gv[14], gv[15]);
            __syncwarp(m1);
            float4 qi = *(const float4*)&sm.g1s[u1v][0][4 * lg];
            float4 qf = *(const float4*)&sm.g1s[u1v][1][4 * lg];
            float4 qg = *(const float4*)&sm.g1s[u1v][2][4 * lg];
            float4 qo = *(const float4*)&sm.g1s[u1v][3][4 * lg];
            float iq[4] = {qi.x, qi.y, qi.z, qi.w};
            float fq[4] = {qf.x, qf.y, qf.z, qf.w};
            float gq[4] = {qg.x, qg.y, qg.z, qg.w};
            float oq[4] = {qo.x, qo.y, qo.z, qo.w};
            #pragma unroll
            for (int j = 0; j < 4; j++) {
                float ig = sigm(iq[j]);
                float fg = sigm(fq[j]);
                float gg = tanh_f(gq[j]);
                float og = sigm(oq[j]);
                c1[j] = fg * c1[j] + ig * gg;
                sm.h1[wb][4 * lg + j][u1v] = og * tanh_f(c1[j]);
            }
        } else if (isL2 && t > 0) {
            // ---- L2 step t-1: reads h1(t-1)=h1[rb], h2(t-2)=h2[wb] ----
            float gv[16];
            for (int cb = 0; cb < BB; cb += CHUNK) {
                ull acc[CHUNK];
                #pragma unroll
                for (int j = 0; j < CHUNK; j++) acc[j] = pack2(bias, 0.0f);
                #pragma unroll
                for (int k4 = 0; k4 < HP1 / 4; k4++) {
                    #pragma unroll
                    for (int j = 0; j < CHUNK; j++) {
                        ulonglong2 v = *((const ulonglong2*)&sm.h1[rb][cb + j][4 * k4]);
                        acc[j] = ffma2(v.x, wreg2[2 * k4],     acc[j]);
                        acc[j] = ffma2(v.y, wreg2[2 * k4 + 1], acc[j]);
                    }
                }
                #pragma unroll
                for (int k4 = 0; k4 < HP2 / 4; k4++) {
                    #pragma unroll
                    for (int j = 0; j < CHUNK; j++) {
                        ulonglong2 v = *((const ulonglong2*)&sm.h2[wb][cb + j][4 * k4]);
                        acc[j] = ffma2(v.x, wreg2[HP1 / 2 + 2 * k4],     acc[j]);
                        acc[j] = ffma2(v.y, wreg2[HP1 / 2 + 2 * k4 + 1], acc[j]);
                    }
                }
                #pragma unroll
                for (int j = 0; j < CHUNK; j++) {
                    float lo, hi; unpack2(acc[j], lo, hi);
                    gv[cb + j] = lo + hi;
                }
            }
            *(float4*)&sm.g2s[u2v][lg2][0]  = make_float4(gv[0],  gv[1],  gv[2],  gv[3]);
            *(float4*)&sm.g2s[u2v][lg2][4]  = make_float4(gv[4],  gv[5],  gv[6],  gv[7]);
            *(float4*)&sm.g2s[u2v][lg2][8]  = make_float4(gv[8],  gv[9],  gv[10], gv[11]);
            *(float4*)&sm.g2s[u2v][lg2][12] = make_float4(gv[12], gv[13], gv[14], gv[15]);
            __syncwarp(m2);
            float4 qi = *(const float4*)&sm.g2s[u2v][0][4 * lg2];
            float4 qf = *(const float4*)&sm.g2s[u2v][1][4 * lg2];
            float4 qg = *(const float4*)&sm.g2s[u2v][2][4 * lg2];
            float4 qo = *(const float4*)&sm.g2s[u2v][3][4 * lg2];
            float iq[4] = {qi.x, qi.y, qi.z, qi.w};
            float fq[4] = {qf.x, qf.y, qf.z, qf.w};
            float gq[4] = {qg.x, qg.y, qg.z, qg.w};
            float oq[4] = {qo.x, qo.y, qo.z, qo.w};
            #pragma unroll
            for (int j = 0; j < 4; j++) {
                float ig = sigm(iq[j]);
                float fg = sigm(fq[j]);
                float gg = tanh_f(gq[j]);
                float og = sigm(oq[j]);
                c2[j] = fg * c2[j] + ig * gg;
                sm.h2[rb][4 * lg2 + j][u2v] = og * tanh_f(c2[j]);
            }
        }
        __syncthreads();   // the ONLY full barrier per step
    }

    // =================== FC head: h2(T-1) lives in buffer (T_LEN-1)&1 ===================
    if (tid < BB * NC) {
        int bb = tid / NC, nc = tid - bb * NC;
        float s = b_fc[nc];
        #pragma unroll
        for (int k = 0; k < H2; k++)
            s = fmaf(sm.h2[(T_LEN - 1) & 1][bb][k], w_fc[nc * H2 + k], s);
        out[(long)(bbase + bb) * NC + nc] = s;
    }
}

extern "C" void kernel_launch(void* const* d_in, const int* in_sizes, int n_in,
                              void* d_out, int out_size)
{
    const float* x     = (const float*)d_in[0];
    const float* w_ih1 = (const float*)d_in[1];
    const float* w_hh1 = (const float*)d_in[2];
    const float* b_ih1 = (const float*)d_in[3];
    const float* b_hh1 = (const float*)d_in[4];
    const float* w_ih2 = (const float*)d_in[5];
    const float* w_hh2 = (const float*)d_in[6];
    const float* b_ih2 = (const float*)d_in[7];
    const float* b_hh2 = (const float*)d_in[8];
    const float* w_fc  = (const float*)d_in[9];
    const float* b_fc  = (const float*)d_in[10];
    float* out = (float*)d_out;

    lstm2_kernel<<<BATCH / BB, THREADS>>>(x, w_ih1, w_hh1, b_ih1, b_hh1,
                                          w_ih2, w_hh2, b_ih2, b_hh2,
                                          w_fc, b_fc, out);
}